// round 7
// baseline (speedup 1.0000x reference)
#include <cuda_runtime.h>
#include <cuda_bf16.h>
#include <math_constants.h>
#include <cstdint>

// VectorQuantizer (per-dimension scalar codebooks), SINGLE fused kernel:
//   Phase A: blocks [0,128) bitonic-sort one codebook dim -> global codes+midpoints
//   (software grid barrier: all blocks co-resident in wave 1)
//   Phase B: all blocks do 4-dim-grouped lower_bound searches + MSE loss
//   z: [B, D] f32 (B=2048, D=128); codebooks: [D, K] f32 (K=512)

#define VQ_D 128
#define VQ_K 512
#define VQ_THREADS 256
#define NDIMS 4
#define PADIDX(i) ((i) + ((i) >> 5))
#define PADK (VQ_K + (VQ_K >> 5))            // 528

__device__ float4       g_code4[VQ_D * VQ_K / 4];
__device__ float4       g_mid4 [VQ_D * VQ_K / 4];
__device__ float        g_partials[1024];
__device__ unsigned int g_count = 0;
__device__ unsigned int g_sort_done = 0;

__global__ void __launch_bounds__(VQ_THREADS)
vq_fused_kernel(const float4* __restrict__ z4,
                const float* __restrict__ cb,
                float* __restrict__ qout,      // may be null
                float* __restrict__ loss_out,  // may be null
                int nb, float inv_n, int vec_ok)
{
    __shared__ float smid [NDIMS][PADK];
    __shared__ float scode[NDIMS][PADK];
    __shared__ float swred[VQ_THREADS / 32];
    __shared__ float sblock;
    __shared__ int   s_is_last;

    const int tid    = threadIdx.x;
    const int lane   = tid & 31;
    const int wid    = tid >> 5;
    const int dg     = blockIdx.x;                       // dim group 0..31
    const int d0     = dg * NDIMS;
    const int bindex = blockIdx.y * gridDim.x + blockIdx.x;
    const int nblocks = gridDim.x * gridDim.y;
    const int sort_blocks = (nblocks < VQ_D) ? nblocks : VQ_D;

    // ---- prefetch z early (independent of sort) ----
    const int b = blockIdx.y * VQ_THREADS + tid;
    const bool v = (b < nb);
    float4 zv = v ? z4[b * (VQ_D / 4) + dg] : make_float4(0.f, 0.f, 0.f, 0.f);

    // ================= Phase A: sort (blocks < sort_blocks) =================
    if (bindex < sort_blocks) {
        float* s = &smid[0][0];   // 512-float scratch (overwritten in Phase B)
        for (int d = bindex; d < VQ_D; d += sort_blocks) {
            if (tid < VQ_K / 4)
                reinterpret_cast<float4*>(s)[tid] =
                    reinterpret_cast<const float4*>(cb + d * VQ_K)[tid];

            for (int k = 2; k <= VQ_K; k <<= 1) {
                for (int j = k >> 1; j > 0; j >>= 1) {
                    __syncthreads();
#pragma unroll
                    for (int t = 0; t < VQ_K / VQ_THREADS; t++) {
                        int i   = tid + t * VQ_THREADS;
                        int ixj = i ^ j;
                        if (ixj > i) {
                            float a = s[i], bb = s[ixj];
                            bool up = ((i & k) == 0);
                            if ((a > bb) == up) { s[i] = bb; s[ixj] = a; }
                        }
                    }
                }
            }
            __syncthreads();

            float* gc = reinterpret_cast<float*>(g_code4);
            float* gm = reinterpret_cast<float*>(g_mid4);
#pragma unroll
            for (int t = 0; t < VQ_K / VQ_THREADS; t++) {
                int i = tid + t * VQ_THREADS;
                float c  = s[i];
                float cn = (i < VQ_K - 1) ? s[i + 1] : 0.0f;
                gc[d * VQ_K + i] = c;
                gm[d * VQ_K + i] = (i < VQ_K - 1) ? 0.5f * (c + cn) : CUDART_INF_F;
            }
            __syncthreads();
        }
        __threadfence();
        __syncthreads();
        if (tid == 0) atomicAdd(&g_sort_done, 1u);
    }

    // ================= grid barrier (all blocks wave-1 resident) ============
    if (tid == 0) {
        while (*((volatile unsigned int*)&g_sort_done) < (unsigned int)sort_blocks) { }
    }
    __syncthreads();
    __threadfence();   // order: barrier pass before staging loads

    // ================= Phase B: stage + search ==============================
#pragma unroll
    for (int i = tid; i < NDIMS * (VQ_K / 4); i += VQ_THREADS) {
        int di = i >> 7;
        int e4 = i & 127;
        int e  = e4 * 4;
        float4 m = g_mid4[(d0 + di) * (VQ_K / 4) + e4];
        smid[di][PADIDX(e + 0)] = m.x;
        smid[di][PADIDX(e + 1)] = m.y;
        smid[di][PADIDX(e + 2)] = m.z;
        smid[di][PADIDX(e + 3)] = m.w;
        float4 c = g_code4[(d0 + di) * (VQ_K / 4) + e4];
        scode[di][PADIDX(e + 0)] = c.x;
        scode[di][PADIDX(e + 1)] = c.y;
        scode[di][PADIDX(e + 2)] = c.z;
        scode[di][PADIDX(e + 3)] = c.w;
    }
    __syncthreads();

    int p0 = 0, p1 = 0, p2 = 0, p3 = 0;
#pragma unroll
    for (int step = VQ_K / 2; step >= 1; step >>= 1) {
        if (smid[0][PADIDX(p0 + step - 1)] < zv.x) p0 += step;
        if (smid[1][PADIDX(p1 + step - 1)] < zv.y) p1 += step;
        if (smid[2][PADIDX(p2 + step - 1)] < zv.z) p2 += step;
        if (smid[3][PADIDX(p3 + step - 1)] < zv.w) p3 += step;
    }
    float q0 = scode[0][PADIDX(p0)];
    float q1 = scode[1][PADIDX(p1)];
    float q2 = scode[2][PADIDX(p2)];
    float q3 = scode[3][PADIDX(p3)];

    float acc = 0.0f;
    if (v) {
        float e0 = q0 - zv.x, e1 = q1 - zv.y, e2 = q2 - zv.z, e3 = q3 - zv.w;
        acc = e0 * e0 + e1 * e1 + e2 * e2 + e3 * e3;
        if (qout) {
            float o0 = zv.x + (q0 - zv.x);
            float o1 = zv.y + (q1 - zv.y);
            float o2 = zv.z + (q2 - zv.z);
            float o3 = zv.w + (q3 - zv.w);
            if (vec_ok) {
                reinterpret_cast<float4*>(qout)[b * (VQ_D / 4) + dg] =
                    make_float4(o0, o1, o2, o3);
            } else {
                float* qp = qout + b * VQ_D + d0;
                qp[0] = o0; qp[1] = o1; qp[2] = o2; qp[3] = o3;
            }
        }
    }

    // ---- block loss reduction (deterministic) ----
#pragma unroll
    for (int o = 16; o > 0; o >>= 1)
        acc += __shfl_down_sync(0xffffffffu, acc, o);
    if (lane == 0) swred[wid] = acc;
    __syncthreads();
    if (tid == 0) {
        float t = 0.0f;
#pragma unroll
        for (int w = 0; w < VQ_THREADS / 32; w++) t += swred[w];
        sblock = t;
    }
    __syncthreads();

    // ---- cross-block finalize (last block; also resets counters) ----
    if (tid == 0) {
        g_partials[bindex] = sblock;
        __threadfence();
        unsigned int c = atomicAdd(&g_count, 1u);
        s_is_last = (c == (unsigned int)(nblocks - 1));
    }
    __syncthreads();

    if (s_is_last && tid < 32) {
        __threadfence();
        float t = 0.0f;
        for (int i = lane; i < nblocks; i += 32)
            t += g_partials[i];
#pragma unroll
        for (int o = 16; o > 0; o >>= 1)
            t += __shfl_down_sync(0xffffffffu, t, o);
        if (lane == 0) {
            if (loss_out) *loss_out = t * inv_n;
            g_count = 0;       // reset for next graph replay
            g_sort_done = 0;   // (all blocks already passed the spin)
        }
    }
}

extern "C" void kernel_launch(void* const* d_in, const int* in_sizes, int n_in,
                              void* d_out, int out_size)
{
    const float* z  = (const float*)d_in[0];   // [B, D]
    const float* cb = (const float*)d_in[1];   // [D, K]
    float* out = (float*)d_out;

    const int nb       = in_sizes[0] / VQ_D;   // B
    const int bd_total = nb * VQ_D;

    float* loss_ptr = nullptr;
    float* q_ptr    = nullptr;
    if (out_size == bd_total + 1)      { loss_ptr = out; q_ptr = out + 1; }
    else if (out_size == bd_total)     { q_ptr = out; }
    else if (out_size == 1)            { loss_ptr = out; }
    else                               { q_ptr = out; }

    int chunks = (nb + VQ_THREADS - 1) / VQ_THREADS;   // 8 for B=2048
    if (chunks > 32) chunks = 32;                      // g_partials bound

    float inv_n = 1.0f / (float)bd_total;
    int vec_ok = (q_ptr != nullptr) && ((((std::uintptr_t)q_ptr) & 15) == 0);

    dim3 grid(VQ_D / NDIMS, chunks);   // (32, 8) = 256 blocks, all wave-1 resident
    vq_fused_kernel<<<grid, VQ_THREADS>>>(
        (const float4*)z, cb, q_ptr, loss_ptr, nb, inv_n, vec_ok);
}

// round 9
// speedup vs baseline: 1.1537x; 1.1537x over previous
#include <cuda_runtime.h>
#include <cuda_bf16.h>
#include <math_constants.h>
#include <cstdint>

// VectorQuantizer (per-dimension scalar codebooks), two-phase:
//   K1: per-dim hybrid bitonic sort (warp-shuffle for j<=32, smem for j>=64)
//       -> global sorted codes + Voronoi midpoints
//   K2: 8-dim-grouped lower_bound on midpoints -> quantized + MSE loss
//   z: [B, D] f32 (B=2048, D=128); codebooks: [D, K] f32 (K=512)

#define VQ_D 128
#define VQ_K 512
#define VQ_THREADS 256          // sort kernel threads (8 warps = 8 chunks of 64)
#define STHREADS 128            // search kernel threads
#define NDIMS 8                 // dims per search block
#define PADIDX(i) ((i) + ((i) >> 5))
#define PADK (VQ_K + (VQ_K >> 5))            // 528

__device__ float4       g_code4[VQ_D * VQ_K / 4];
__device__ float4       g_mid4 [VQ_D * VQ_K / 4];
__device__ float        g_partials[1024];
__device__ unsigned int g_count = 0;

// compare-exchange across lanes: element x at global index i, partner i^j (j<=16)
__device__ __forceinline__ float cmpx(float x, int i, int j, int k)
{
    float y = __shfl_xor_sync(0xffffffffu, x, j);
    bool keepmin = (((i & j) == 0) == ((i & k) == 0));
    return keepmin ? fminf(x, y) : fmaxf(x, y);
}

// ---------------- Kernel 1: hybrid bitonic sort + midpoints ----------------
__global__ void __launch_bounds__(VQ_THREADS)
vq_sort_kernel(const float* __restrict__ cb)
{
    __shared__ float s[VQ_K];
    const int d    = blockIdx.x;
    const int tid  = threadIdx.x;
    const int l    = tid & 31;
    const int w    = tid >> 5;
    const int base = w * 64;           // this warp's 64-element chunk

    // load chunk directly to registers (coalesced)
    float a = cb[d * VQ_K + base + l];
    float b = cb[d * VQ_K + base + 32 + l];

    // ---- in-warp bitonic: k = 2..32 (both halves independently) ----
#pragma unroll
    for (int k = 2; k <= 32; k <<= 1) {
#pragma unroll
        for (int j = k >> 1; j >= 1; j >>= 1) {
            a = cmpx(a, base + l,      j, k);
            b = cmpx(b, base + 32 + l, j, k);
        }
    }
    // ---- k = 64: j=32 in-lane, then j=16..1 shuffles ----
    {
        bool up = ((base & 64) == 0);
        if ((a > b) == up) { float t = a; a = b; b = t; }
#pragma unroll
        for (int j = 16; j >= 1; j >>= 1) {
            a = cmpx(a, base + l,      j, 64);
            b = cmpx(b, base + 32 + l, j, 64);
        }
    }
    s[base + l]      = a;
    s[base + 32 + l] = b;

    // ---- k = 128, 256, 512: j>=64 via smem, j<=32 in-warp ----
    for (int k = 128; k <= VQ_K; k <<= 1) {
        for (int j = k >> 1; j >= 64; j >>= 1) {
            __syncthreads();
#pragma unroll
            for (int t = 0; t < VQ_K / VQ_THREADS; t++) {
                int i   = tid + t * VQ_THREADS;
                int ixj = i ^ j;
                if (ixj > i) {
                    float x = s[i], y = s[ixj];
                    bool up = ((i & k) == 0);
                    if ((x > y) == up) { s[i] = y; s[ixj] = x; }
                }
            }
        }
        __syncthreads();
        a = s[base + l];
        b = s[base + 32 + l];
        bool up = ((base & k) == 0);       // i&k uniform within chunk (k>=64)
        if ((a > b) == up) { float t = a; a = b; b = t; }
#pragma unroll
        for (int j = 16; j >= 1; j >>= 1) {
            a = cmpx(a, base + l,      j, k);
            b = cmpx(b, base + 32 + l, j, k);
        }
        s[base + l]      = a;
        s[base + 32 + l] = b;
    }
    __syncthreads();

    // ---- write sorted codes + midpoints ----
    float* gc = reinterpret_cast<float*>(g_code4);
    float* gm = reinterpret_cast<float*>(g_mid4);
#pragma unroll
    for (int t = 0; t < VQ_K / VQ_THREADS; t++) {
        int i = tid + t * VQ_THREADS;
        float c  = s[i];
        float cn = (i < VQ_K - 1) ? s[i + 1] : 0.0f;
        gc[d * VQ_K + i] = c;
        gm[d * VQ_K + i] = (i < VQ_K - 1) ? 0.5f * (c + cn) : CUDART_INF_F;
    }
}

// ---------------- Kernel 2: 8-dim grouped search + loss ----------------
__global__ void __launch_bounds__(STHREADS)
vq_search_kernel(const float4* __restrict__ z4,
                 float* __restrict__ qout,      // may be null
                 float* __restrict__ loss_out,  // may be null
                 int nb, float inv_n, int vec_ok)
{
    __shared__ float smid [NDIMS][PADK];
    __shared__ float scode[NDIMS][PADK];
    __shared__ float swred[STHREADS / 32];
    __shared__ float sblock;
    __shared__ int   s_is_last;

    const int dg   = blockIdx.x;          // dim group 0..15 (8 dims each)
    const int d0   = dg * NDIMS;
    const int tid  = threadIdx.x;
    const int lane = tid & 31;
    const int wid  = tid >> 5;

    // prefetch z: 8 dims for one b = 32 contiguous bytes (2 float4)
    const int b = blockIdx.y * STHREADS + tid;
    const bool v = (b < nb);
    float4 za = make_float4(0.f, 0.f, 0.f, 0.f), zb = za;
    if (v) {
        za = z4[b * (VQ_D / 4) + dg * 2 + 0];
        zb = z4[b * (VQ_D / 4) + dg * 2 + 1];
    }
    float zr[NDIMS] = { za.x, za.y, za.z, za.w, zb.x, zb.y, zb.z, zb.w };

    // stage 8 dims' midpoints + codes (padded)
    for (int i = tid; i < NDIMS * (VQ_K / 4); i += STHREADS) {
        int di = i >> 7;             // 128 float4 per dim
        int e4 = i & 127;
        int e  = e4 * 4;
        float4 m = g_mid4[(d0 + di) * (VQ_K / 4) + e4];
        smid[di][PADIDX(e + 0)] = m.x;
        smid[di][PADIDX(e + 1)] = m.y;
        smid[di][PADIDX(e + 2)] = m.z;
        smid[di][PADIDX(e + 3)] = m.w;
        float4 c = g_code4[(d0 + di) * (VQ_K / 4) + e4];
        scode[di][PADIDX(e + 0)] = c.x;
        scode[di][PADIDX(e + 1)] = c.y;
        scode[di][PADIDX(e + 2)] = c.z;
        scode[di][PADIDX(e + 3)] = c.w;
    }
    __syncthreads();

    // 8 interleaved lower_bound searches (ILP-8 hides LDS latency)
    int p[NDIMS];
#pragma unroll
    for (int di = 0; di < NDIMS; di++) p[di] = 0;
#pragma unroll
    for (int step = VQ_K / 2; step >= 1; step >>= 1) {
#pragma unroll
        for (int di = 0; di < NDIMS; di++)
            if (smid[di][PADIDX(p[di] + step - 1)] < zr[di]) p[di] += step;
    }
    float q[NDIMS];
#pragma unroll
    for (int di = 0; di < NDIMS; di++)
        q[di] = scode[di][PADIDX(p[di])];

    float acc = 0.0f;
    if (v) {
#pragma unroll
        for (int di = 0; di < NDIMS; di++) {
            float e = q[di] - zr[di];
            acc += e * e;
        }
        if (qout) {
            float o[NDIMS];
#pragma unroll
            for (int di = 0; di < NDIMS; di++)
                o[di] = zr[di] + (q[di] - zr[di]);   // ST value
            if (vec_ok) {
                reinterpret_cast<float4*>(qout)[b * (VQ_D / 4) + dg * 2 + 0] =
                    make_float4(o[0], o[1], o[2], o[3]);
                reinterpret_cast<float4*>(qout)[b * (VQ_D / 4) + dg * 2 + 1] =
                    make_float4(o[4], o[5], o[6], o[7]);
            } else {
                float* qp = qout + b * VQ_D + d0;
#pragma unroll
                for (int di = 0; di < NDIMS; di++) qp[di] = o[di];
            }
        }
    }

    // block loss reduction (deterministic)
#pragma unroll
    for (int o = 16; o > 0; o >>= 1)
        acc += __shfl_down_sync(0xffffffffu, acc, o);
    if (lane == 0) swred[wid] = acc;
    __syncthreads();
    if (tid == 0) {
        float t = 0.0f;
#pragma unroll
        for (int ww = 0; ww < STHREADS / 32; ww++) t += swred[ww];
        sblock = t;
    }
    __syncthreads();

    // cross-block finalize (last block, deterministic order)
    const int nblocks = gridDim.x * gridDim.y;
    const int bindex  = blockIdx.y * gridDim.x + blockIdx.x;
    if (tid == 0) {
        g_partials[bindex] = sblock;
        __threadfence();
        unsigned int c = atomicAdd(&g_count, 1u);
        s_is_last = (c == (unsigned int)(nblocks - 1));
    }
    __syncthreads();

    if (s_is_last && tid < 32) {
        __threadfence();
        float t = 0.0f;
        for (int i = lane; i < nblocks; i += 32)
            t += g_partials[i];
#pragma unroll
        for (int o = 16; o > 0; o >>= 1)
            t += __shfl_down_sync(0xffffffffu, t, o);
        if (lane == 0) {
            if (loss_out) *loss_out = t * inv_n;
            g_count = 0;   // reset for next graph replay
        }
    }
}

extern "C" void kernel_launch(void* const* d_in, const int* in_sizes, int n_in,
                              void* d_out, int out_size)
{
    const float* z  = (const float*)d_in[0];   // [B, D]
    const float* cb = (const float*)d_in[1];   // [D, K]
    float* out = (float*)d_out;

    const int nb       = in_sizes[0] / VQ_D;   // B
    const int bd_total = nb * VQ_D;

    float* loss_ptr = nullptr;
    float* q_ptr    = nullptr;
    if (out_size == bd_total + 1)      { loss_ptr = out; q_ptr = out + 1; }
    else if (out_size == bd_total)     { q_ptr = out; }
    else if (out_size == 1)            { loss_ptr = out; }
    else                               { q_ptr = out; }

    int chunks = (nb + STHREADS - 1) / STHREADS;   // 16 for B=2048
    if (chunks > 64) chunks = 64;                  // g_partials bound (64*16=1024)

    float inv_n = 1.0f / (float)bd_total;
    int vec_ok = (q_ptr != nullptr) && ((((std::uintptr_t)q_ptr) & 15) == 0);

    vq_sort_kernel<<<VQ_D, VQ_THREADS>>>(cb);
    dim3 grid(VQ_D / NDIMS, chunks);               // (16, 16) = 256 blocks
    vq_search_kernel<<<grid, STHREADS>>>(
        (const float4*)z, q_ptr, loss_ptr, nb, inv_n, vec_ok);
}

// round 10
// speedup vs baseline: 1.3632x; 1.1816x over previous
#include <cuda_runtime.h>
#include <cuda_bf16.h>
#include <math_constants.h>
#include <cstdint>

// VectorQuantizer (per-dimension scalar codebooks), two-phase:
//   K1: per-dim hybrid bitonic sort (warp shuffles; smem only for j>=64)
//       -> global sorted codes + Voronoi midpoints
//   K2: 4-dim-grouped lower_bound on smem midpoints; final code gather from L2
//   z: [B, D] f32 (B=2048, D=128); codebooks: [D, K] f32 (K=512)

#define VQ_D 128
#define VQ_K 512
#define VQ_THREADS 256          // both kernels
#define NDIMS 4                 // dims per search block
#define PADIDX(i) ((i) + ((i) >> 5))
#define PADK (VQ_K + (VQ_K >> 5))            // 528

__device__ float        g_code[VQ_D * VQ_K];
__device__ float4       g_mid4[VQ_D * VQ_K / 4];
__device__ float        g_partials[1024];
__device__ unsigned int g_count = 0;

// compare-exchange across lanes: element x at global index i, partner i^j (j<=16)
__device__ __forceinline__ float cmpx(float x, int i, int j, int k)
{
    float y = __shfl_xor_sync(0xffffffffu, x, j);
    bool keepmin = (((i & j) == 0) == ((i & k) == 0));
    return keepmin ? fminf(x, y) : fmaxf(x, y);
}

// ---------------- Kernel 1: hybrid bitonic sort + midpoints ----------------
__global__ void __launch_bounds__(VQ_THREADS)
vq_sort_kernel(const float* __restrict__ cb)
{
    __shared__ float s[VQ_K];
    const int d    = blockIdx.x;
    const int tid  = threadIdx.x;
    const int l    = tid & 31;
    const int w    = tid >> 5;
    const int base = w * 64;           // this warp's 64-element chunk

    float a = cb[d * VQ_K + base + l];
    float b = cb[d * VQ_K + base + 32 + l];

    // in-warp bitonic: k = 2..32
#pragma unroll
    for (int k = 2; k <= 32; k <<= 1) {
#pragma unroll
        for (int j = k >> 1; j >= 1; j >>= 1) {
            a = cmpx(a, base + l,      j, k);
            b = cmpx(b, base + 32 + l, j, k);
        }
    }
    // k = 64: j=32 in-lane, then j=16..1 shuffles
    {
        bool up = ((base & 64) == 0);
        if ((a > b) == up) { float t = a; a = b; b = t; }
#pragma unroll
        for (int j = 16; j >= 1; j >>= 1) {
            a = cmpx(a, base + l,      j, 64);
            b = cmpx(b, base + 32 + l, j, 64);
        }
    }
    s[base + l]      = a;
    s[base + 32 + l] = b;

    // k = 128, 256, 512: j>=64 via smem, j<=32 in-warp
    for (int k = 128; k <= VQ_K; k <<= 1) {
        for (int j = k >> 1; j >= 64; j >>= 1) {
            __syncthreads();
#pragma unroll
            for (int t = 0; t < VQ_K / VQ_THREADS; t++) {
                int i   = tid + t * VQ_THREADS;
                int ixj = i ^ j;
                if (ixj > i) {
                    float x = s[i], y = s[ixj];
                    bool up = ((i & k) == 0);
                    if ((x > y) == up) { s[i] = y; s[ixj] = x; }
                }
            }
        }
        __syncthreads();
        a = s[base + l];
        b = s[base + 32 + l];
        bool up = ((base & k) == 0);
        if ((a > b) == up) { float t = a; a = b; b = t; }
#pragma unroll
        for (int j = 16; j >= 1; j >>= 1) {
            a = cmpx(a, base + l,      j, k);
            b = cmpx(b, base + 32 + l, j, k);
        }
        s[base + l]      = a;
        s[base + 32 + l] = b;
    }
    __syncthreads();

    float* gm = reinterpret_cast<float*>(g_mid4);
#pragma unroll
    for (int t = 0; t < VQ_K / VQ_THREADS; t++) {
        int i = tid + t * VQ_THREADS;
        float c  = s[i];
        float cn = (i < VQ_K - 1) ? s[i + 1] : 0.0f;
        g_code[d * VQ_K + i] = c;
        gm[d * VQ_K + i] = (i < VQ_K - 1) ? 0.5f * (c + cn) : CUDART_INF_F;
    }
}

// ---------------- Kernel 2: search (mid-only smem) + loss ----------------
__global__ void __launch_bounds__(VQ_THREADS)
vq_search_kernel(const float4* __restrict__ z4,
                 float* __restrict__ qout,      // may be null
                 float* __restrict__ loss_out,  // may be null
                 int nb, float inv_n, int vec_ok)
{
    __shared__ float smid[NDIMS][PADK];
    __shared__ float swred[VQ_THREADS / 32];
    __shared__ float sblock;
    __shared__ int   s_is_last;

    const int dg   = blockIdx.x;          // dim group 0..31
    const int d0   = dg * NDIMS;
    const int tid  = threadIdx.x;
    const int lane = tid & 31;
    const int wid  = tid >> 5;

    // prefetch z (one float4 = 4 dims for one b)
    const int b = blockIdx.y * VQ_THREADS + tid;
    const bool v = (b < nb);
    float4 zv = v ? z4[b * (VQ_D / 4) + dg] : make_float4(0.f, 0.f, 0.f, 0.f);

    // stage 4 dims' midpoints (padded): 512 float4 loads, 2 per thread
#pragma unroll
    for (int i = tid; i < NDIMS * (VQ_K / 4); i += VQ_THREADS) {
        int di = i >> 7;
        int e4 = i & 127;
        int e  = e4 * 4;
        float4 m = g_mid4[(d0 + di) * (VQ_K / 4) + e4];
        smid[di][PADIDX(e + 0)] = m.x;
        smid[di][PADIDX(e + 1)] = m.y;
        smid[di][PADIDX(e + 2)] = m.z;
        smid[di][PADIDX(e + 3)] = m.w;
    }
    __syncthreads();

    // 4 interleaved lower_bound searches (ILP hides LDS latency)
    int p0 = 0, p1 = 0, p2 = 0, p3 = 0;
#pragma unroll
    for (int step = VQ_K / 2; step >= 1; step >>= 1) {
        if (smid[0][PADIDX(p0 + step - 1)] < zv.x) p0 += step;
        if (smid[1][PADIDX(p1 + step - 1)] < zv.y) p1 += step;
        if (smid[2][PADIDX(p2 + step - 1)] < zv.z) p2 += step;
        if (smid[3][PADIDX(p3 + step - 1)] < zv.w) p3 += step;
    }
    // final code gather from L2-hot global (independent loads)
    float q0 = __ldg(&g_code[(d0 + 0) * VQ_K + p0]);
    float q1 = __ldg(&g_code[(d0 + 1) * VQ_K + p1]);
    float q2 = __ldg(&g_code[(d0 + 2) * VQ_K + p2]);
    float q3 = __ldg(&g_code[(d0 + 3) * VQ_K + p3]);

    float acc = 0.0f;
    if (v) {
        float e0 = q0 - zv.x, e1 = q1 - zv.y, e2 = q2 - zv.z, e3 = q3 - zv.w;
        acc = e0 * e0 + e1 * e1 + e2 * e2 + e3 * e3;
        if (qout) {
            float o0 = zv.x + (q0 - zv.x);
            float o1 = zv.y + (q1 - zv.y);
            float o2 = zv.z + (q2 - zv.z);
            float o3 = zv.w + (q3 - zv.w);
            if (vec_ok) {
                reinterpret_cast<float4*>(qout)[b * (VQ_D / 4) + dg] =
                    make_float4(o0, o1, o2, o3);
            } else {
                float* qp = qout + b * VQ_D + d0;
                qp[0] = o0; qp[1] = o1; qp[2] = o2; qp[3] = o3;
            }
        }
    }

    // block loss reduction (deterministic)
#pragma unroll
    for (int o = 16; o > 0; o >>= 1)
        acc += __shfl_down_sync(0xffffffffu, acc, o);
    if (lane == 0) swred[wid] = acc;
    __syncthreads();
    if (tid == 0) {
        float t = 0.0f;
#pragma unroll
        for (int ww = 0; ww < VQ_THREADS / 32; ww++) t += swred[ww];
        sblock = t;
    }
    __syncthreads();

    // cross-block finalize (last block, deterministic order)
    const int nblocks = gridDim.x * gridDim.y;
    const int bindex  = blockIdx.y * gridDim.x + blockIdx.x;
    if (tid == 0) {
        g_partials[bindex] = sblock;
        __threadfence();
        unsigned int c = atomicAdd(&g_count, 1u);
        s_is_last = (c == (unsigned int)(nblocks - 1));
    }
    __syncthreads();

    if (s_is_last && tid < 32) {
        __threadfence();
        float t = 0.0f;
        for (int i = lane; i < nblocks; i += 32)
            t += g_partials[i];
#pragma unroll
        for (int o = 16; o > 0; o >>= 1)
            t += __shfl_down_sync(0xffffffffu, t, o);
        if (lane == 0) {
            if (loss_out) *loss_out = t * inv_n;
            g_count = 0;   // reset for next graph replay
        }
    }
}

extern "C" void kernel_launch(void* const* d_in, const int* in_sizes, int n_in,
                              void* d_out, int out_size)
{
    const float* z  = (const float*)d_in[0];   // [B, D]
    const float* cb = (const float*)d_in[1];   // [D, K]
    float* out = (float*)d_out;

    const int nb       = in_sizes[0] / VQ_D;   // B
    const int bd_total = nb * VQ_D;

    float* loss_ptr = nullptr;
    float* q_ptr    = nullptr;
    if (out_size == bd_total + 1)      { loss_ptr = out; q_ptr = out + 1; }
    else if (out_size == bd_total)     { q_ptr = out; }
    else if (out_size == 1)            { loss_ptr = out; }
    else                               { q_ptr = out; }

    int chunks = (nb + VQ_THREADS - 1) / VQ_THREADS;   // 8 for B=2048
    if (chunks > 32) chunks = 32;                      // g_partials bound

    float inv_n = 1.0f / (float)bd_total;
    int vec_ok = (q_ptr != nullptr) && ((((std::uintptr_t)q_ptr) & 15) == 0);

    vq_sort_kernel<<<VQ_D, VQ_THREADS>>>(cb);
    dim3 grid(VQ_D / NDIMS, chunks);               // (32, 8) = 256 blocks
    vq_search_kernel<<<grid, VQ_THREADS>>>(
        (const float4*)z, q_ptr, loss_ptr, nb, inv_n, vec_ok);
}